// round 1
// baseline (speedup 1.0000x reference)
#include <cuda_runtime.h>
#include <math.h>

// ---------------------------------------------------------------------------
// GraphTrajectoryEncoder: B=4, S=1024, D=512, DEPTH=6, H=8, HD=64, F=2048
// Full fp32 baseline. Per layer:
//   LN1 -> QKV gemm -> masked QK^T -> softmax -> PV -> Wout(+bias+res)
//   LN2 -> FF1(+bias,gelu) -> FF2(+bias+res)
// ---------------------------------------------------------------------------

namespace {
constexpr int Bc = 4, Sc = 1024, Dc = 512, Hc = 8, HDc = 64, Fc = 2048;
constexpr int INNERc = 512;
constexpr int QKVC = 3 * INNERc;   // 1536
constexpr int Mr = Bc * Sc;        // 4096
}

// Scratch (allocation-free: module globals)
__device__ __align__(128) float g_n[Mr * Dc];
__device__ __align__(128) float g_qkv[Mr * QKVC];
__device__ __align__(128) float g_scores[(size_t)Bc * Hc * Sc * Sc];  // 128 MB
__device__ __align__(128) float g_o[Mr * INNERc];
__device__ __align__(128) float g_ff[Mr * Fc];
__device__ __align__(128) float g_h[Mr * Dc];

// ---------------------------------------------------------------------------
// Block-wide reduction for 256 threads
// ---------------------------------------------------------------------------
template <bool MAXOP>
__device__ __forceinline__ float block_reduce256(float v) {
    __shared__ float red[8];
    const int t = threadIdx.x;
#pragma unroll
    for (int o = 16; o > 0; o >>= 1) {
        float u = __shfl_down_sync(0xffffffffu, v, o);
        v = MAXOP ? fmaxf(v, u) : v + u;
    }
    if ((t & 31) == 0) red[t >> 5] = v;
    __syncthreads();
    if (t < 32) {
        v = (t < 8) ? red[t] : (MAXOP ? -INFINITY : 0.0f);
#pragma unroll
        for (int o = 4; o > 0; o >>= 1) {
            float u = __shfl_down_sync(0xffffffffu, v, o);
            v = MAXOP ? fmaxf(v, u) : v + u;
        }
        if (t == 0) red[0] = v;
    }
    __syncthreads();
    float r = red[0];
    __syncthreads();  // allow safe reuse of red[] by a subsequent call
    return r;
}

// ---------------------------------------------------------------------------
// LayerNorm over D=512, one block (256 threads) per row, 2 elems/thread
// ---------------------------------------------------------------------------
__global__ void ln_kernel(const float* __restrict__ h, const float* __restrict__ w,
                          const float* __restrict__ b, float* __restrict__ out) {
    const int row = blockIdx.x;
    const int t = threadIdx.x;
    const float2 v = *reinterpret_cast<const float2*>(h + (size_t)row * Dc + t * 2);
    const float mean = block_reduce256<false>(v.x + v.y) * (1.0f / Dc);
    const float d0 = v.x - mean, d1 = v.y - mean;
    const float var = block_reduce256<false>(d0 * d0 + d1 * d1) * (1.0f / Dc);
    const float rstd = rsqrtf(var + 1e-5f);
    const float2 ww = *reinterpret_cast<const float2*>(w + t * 2);
    const float2 bb = *reinterpret_cast<const float2*>(b + t * 2);
    float2 o2 = make_float2(d0 * rstd * ww.x + bb.x, d1 * rstd * ww.y + bb.y);
    *reinterpret_cast<float2*>(out + (size_t)row * Dc + t * 2) = o2;
}

// ---------------------------------------------------------------------------
// Generic NN GEMM, 128x128 tile, BK=8, 256 threads, 8x8 micro-tile.
// C[M,N] = A[M,K] @ B[K,N]  (+ bias) (gelu) (+ residual)
// M,N multiples of 128; K multiple of 8.
// ---------------------------------------------------------------------------
__global__ void __launch_bounds__(256, 2) gemm128_kernel(
    const float* __restrict__ A, const float* __restrict__ B, float* __restrict__ C,
    int M, int N, int K, int lda, int ldb, int ldc,
    const float* __restrict__ bias, const float* __restrict__ res, int gelu) {
    __shared__ float As[8][132];
    __shared__ float Bs[8][132];
    const int tid = threadIdx.x;
    const int row0 = blockIdx.y * 128, col0 = blockIdx.x * 128;
    const int ty = tid >> 4, tx = tid & 15;
    const int ar = tid >> 1, ak = (tid & 1) << 2;
    const int bk = tid >> 5, bn = (tid & 31) << 2;
    const float* Ap = A + (size_t)(row0 + ar) * lda + ak;
    const float* Bp = B + (size_t)bk * ldb + col0 + bn;

    float acc[8][8];
#pragma unroll
    for (int i = 0; i < 8; i++)
#pragma unroll
        for (int j = 0; j < 8; j++) acc[i][j] = 0.0f;

    for (int k0 = 0; k0 < K; k0 += 8) {
        const float4 a = *reinterpret_cast<const float4*>(Ap + k0);
        const float4 bv = *reinterpret_cast<const float4*>(Bp + (size_t)k0 * ldb);
        __syncthreads();
        As[ak + 0][ar] = a.x; As[ak + 1][ar] = a.y;
        As[ak + 2][ar] = a.z; As[ak + 3][ar] = a.w;
        *reinterpret_cast<float4*>(&Bs[bk][bn]) = bv;
        __syncthreads();
#pragma unroll
        for (int k = 0; k < 8; k++) {
            const float4 a0 = *reinterpret_cast<const float4*>(&As[k][ty * 8]);
            const float4 a1 = *reinterpret_cast<const float4*>(&As[k][ty * 8 + 4]);
            const float4 b0 = *reinterpret_cast<const float4*>(&Bs[k][tx * 8]);
            const float4 b1 = *reinterpret_cast<const float4*>(&Bs[k][tx * 8 + 4]);
            const float av[8] = {a0.x, a0.y, a0.z, a0.w, a1.x, a1.y, a1.z, a1.w};
            const float bw[8] = {b0.x, b0.y, b0.z, b0.w, b1.x, b1.y, b1.z, b1.w};
#pragma unroll
            for (int i = 0; i < 8; i++)
#pragma unroll
                for (int j = 0; j < 8; j++)
                    acc[i][j] = fmaf(av[i], bw[j], acc[i][j]);
        }
    }

#pragma unroll
    for (int i = 0; i < 8; i++) {
        const int r = row0 + ty * 8 + i;
#pragma unroll
        for (int j = 0; j < 8; j++) {
            const int c = col0 + tx * 8 + j;
            float v = acc[i][j];
            if (bias) v += __ldg(&bias[c]);
            if (gelu) v = 0.5f * v * (1.0f + erff(v * 0.7071067811865475f));
            if (res) v += res[(size_t)r * ldc + c];
            C[(size_t)r * ldc + c] = v;
        }
    }
}

// ---------------------------------------------------------------------------
// Scores: per (b,h): S[i,j] = keep ? 0.125 * (q_i . k_j) : -1e9
// keep = graph_mask[b,i,j] > 0 || i == j. 128x128 tile, K = HD = 64.
// grid (S/128, S/128, B*H)
// ---------------------------------------------------------------------------
__global__ void __launch_bounds__(256, 2) scores_kernel(
    const float* __restrict__ qkv, const int* __restrict__ gmask,
    float* __restrict__ scores) {
    __shared__ float As[8][132];
    __shared__ float Bs[8][132];
    const int tid = threadIdx.x;
    const int bh = blockIdx.z, b = bh >> 3, hh = bh & 7;
    const float* Q = qkv + (size_t)b * Sc * QKVC + hh * HDc;
    const float* Kp = Q + INNERc;
    const int row0 = blockIdx.y * 128, col0 = blockIdx.x * 128;
    const int ty = tid >> 4, tx = tid & 15;
    const int ar = tid >> 1, ak = (tid & 1) << 2;

    float acc[8][8];
#pragma unroll
    for (int i = 0; i < 8; i++)
#pragma unroll
        for (int j = 0; j < 8; j++) acc[i][j] = 0.0f;

    for (int k0 = 0; k0 < HDc; k0 += 8) {
        const float4 a = *reinterpret_cast<const float4*>(Q + (size_t)(row0 + ar) * QKVC + k0 + ak);
        const float4 kk = *reinterpret_cast<const float4*>(Kp + (size_t)(col0 + ar) * QKVC + k0 + ak);
        __syncthreads();
        As[ak + 0][ar] = a.x; As[ak + 1][ar] = a.y;
        As[ak + 2][ar] = a.z; As[ak + 3][ar] = a.w;
        Bs[ak + 0][ar] = kk.x; Bs[ak + 1][ar] = kk.y;
        Bs[ak + 2][ar] = kk.z; Bs[ak + 3][ar] = kk.w;
        __syncthreads();
#pragma unroll
        for (int k = 0; k < 8; k++) {
            const float4 a0 = *reinterpret_cast<const float4*>(&As[k][ty * 8]);
            const float4 a1 = *reinterpret_cast<const float4*>(&As[k][ty * 8 + 4]);
            const float4 b0 = *reinterpret_cast<const float4*>(&Bs[k][tx * 8]);
            const float4 b1 = *reinterpret_cast<const float4*>(&Bs[k][tx * 8 + 4]);
            const float av[8] = {a0.x, a0.y, a0.z, a0.w, a1.x, a1.y, a1.z, a1.w};
            const float bw[8] = {b0.x, b0.y, b0.z, b0.w, b1.x, b1.y, b1.z, b1.w};
#pragma unroll
            for (int i = 0; i < 8; i++)
#pragma unroll
                for (int j = 0; j < 8; j++)
                    acc[i][j] = fmaf(av[i], bw[j], acc[i][j]);
        }
    }

    float* Sout = scores + (size_t)bh * Sc * Sc;
    const int* Mrow = gmask + (size_t)b * Sc * Sc;
#pragma unroll
    for (int i = 0; i < 8; i++) {
        const int r = row0 + ty * 8 + i;
#pragma unroll
        for (int j = 0; j < 8; j++) {
            const int c = col0 + tx * 8 + j;
            const bool keep = (__ldg(&Mrow[(size_t)r * Sc + c]) > 0) || (r == c);
            Sout[(size_t)r * Sc + c] = keep ? acc[i][j] * 0.125f : -1e9f;
        }
    }
}

// ---------------------------------------------------------------------------
// Softmax in-place over rows of length S=1024. 1 block (256 thr) per row.
// ---------------------------------------------------------------------------
__global__ void softmax_kernel(float* __restrict__ scores) {
    float* p = scores + (size_t)blockIdx.x * Sc;
    const int t = threadIdx.x;
    float4 v = *reinterpret_cast<float4*>(p + t * 4);
    const float m = block_reduce256<true>(fmaxf(fmaxf(v.x, v.y), fmaxf(v.z, v.w)));
    const float e0 = __expf(v.x - m), e1 = __expf(v.y - m);
    const float e2 = __expf(v.z - m), e3 = __expf(v.w - m);
    const float s = block_reduce256<false>(e0 + e1 + e2 + e3);
    const float inv = 1.0f / s;
    *reinterpret_cast<float4*>(p + t * 4) = make_float4(e0 * inv, e1 * inv, e2 * inv, e3 * inv);
}

// ---------------------------------------------------------------------------
// PV: o[b,s,h*64+d] = sum_j probs[bh,s,j] * v[b,j,h*64+d]
// 64x64 tile, BK=16, 256 threads, 4x4 micro-tile. grid (1, S/64, B*H)
// ---------------------------------------------------------------------------
__global__ void __launch_bounds__(256) pv_kernel(
    const float* __restrict__ scores, const float* __restrict__ qkv,
    float* __restrict__ o) {
    __shared__ float Ps[16][68];
    __shared__ float Vs[16][68];
    const int tid = threadIdx.x;
    const int bh = blockIdx.z, b = bh >> 3, hh = bh & 7;
    const float* P = scores + (size_t)bh * Sc * Sc;
    const float* V = qkv + (size_t)b * Sc * QKVC + 2 * INNERc + hh * HDc;
    float* Co = o + (size_t)b * Sc * INNERc + hh * HDc;
    const int row0 = blockIdx.y * 64;
    const int ty = tid >> 4, tx = tid & 15;
    const int pr = tid >> 2, pk = (tid & 3) << 2;
    const int vk = tid >> 4, vn = (tid & 15) << 2;

    float acc[4][4];
#pragma unroll
    for (int i = 0; i < 4; i++)
#pragma unroll
        for (int j = 0; j < 4; j++) acc[i][j] = 0.0f;

    for (int k0 = 0; k0 < Sc; k0 += 16) {
        const float4 p4 = *reinterpret_cast<const float4*>(P + (size_t)(row0 + pr) * Sc + k0 + pk);
        const float4 v4 = *reinterpret_cast<const float4*>(V + (size_t)(k0 + vk) * QKVC + vn);
        __syncthreads();
        Ps[pk + 0][pr] = p4.x; Ps[pk + 1][pr] = p4.y;
        Ps[pk + 2][pr] = p4.z; Ps[pk + 3][pr] = p4.w;
        *reinterpret_cast<float4*>(&Vs[vk][vn]) = v4;
        __syncthreads();
#pragma unroll
        for (int k = 0; k < 16; k++) {
            const float4 a = *reinterpret_cast<const float4*>(&Ps[k][ty * 4]);
            const float4 bb = *reinterpret_cast<const float4*>(&Vs[k][tx * 4]);
            const float av[4] = {a.x, a.y, a.z, a.w};
            const float bw[4] = {bb.x, bb.y, bb.z, bb.w};
#pragma unroll
            for (int i = 0; i < 4; i++)
#pragma unroll
                for (int j = 0; j < 4; j++)
                    acc[i][j] = fmaf(av[i], bw[j], acc[i][j]);
        }
    }

#pragma unroll
    for (int i = 0; i < 4; i++)
#pragma unroll
        for (int j = 0; j < 4; j++)
            Co[(size_t)(row0 + ty * 4 + i) * INNERc + tx * 4 + j] = acc[i][j];
}

// ---------------------------------------------------------------------------
// Host launcher
// ---------------------------------------------------------------------------
extern "C" void kernel_launch(void* const* d_in, const int* in_sizes, int n_in,
                              void* d_out, int out_size) {
    (void)in_sizes; (void)n_in; (void)out_size;
    const float* x    = (const float*)d_in[0];
    const int*   gmask = (const int*)d_in[1];
    const float* ln1w = (const float*)d_in[2];
    const float* ln1b = (const float*)d_in[3];
    const float* Wqkv = (const float*)d_in[4];
    const float* Wout = (const float*)d_in[5];
    const float* bout = (const float*)d_in[6];
    const float* ln2w = (const float*)d_in[7];
    const float* ln2b = (const float*)d_in[8];
    const float* W1   = (const float*)d_in[9];
    const float* b1   = (const float*)d_in[10];
    const float* W2   = (const float*)d_in[11];
    const float* b2   = (const float*)d_in[12];
    float* out = (float*)d_out;

    float *pn, *pqkv, *pscores, *po, *pff, *ph;
    cudaGetSymbolAddress((void**)&pn, g_n);
    cudaGetSymbolAddress((void**)&pqkv, g_qkv);
    cudaGetSymbolAddress((void**)&pscores, g_scores);
    cudaGetSymbolAddress((void**)&po, g_o);
    cudaGetSymbolAddress((void**)&pff, g_ff);
    cudaGetSymbolAddress((void**)&ph, g_h);

    for (int l = 0; l < 6; l++) {
        const float* hin = (l == 0) ? x : ph;

        // --- attention block ---
        ln_kernel<<<Mr, 256>>>(hin, ln1w + l * Dc, ln1b + l * Dc, pn);
        gemm128_kernel<<<dim3(QKVC / 128, Mr / 128), 256>>>(
            pn, Wqkv + (size_t)l * Dc * QKVC, pqkv,
            Mr, QKVC, Dc, Dc, QKVC, QKVC, nullptr, nullptr, 0);
        scores_kernel<<<dim3(Sc / 128, Sc / 128, Bc * Hc), 256>>>(pqkv, gmask, pscores);
        softmax_kernel<<<Bc * Hc * Sc, 256>>>(pscores);
        pv_kernel<<<dim3(1, Sc / 64, Bc * Hc), 256>>>(pscores, pqkv, po);
        gemm128_kernel<<<dim3(Dc / 128, Mr / 128), 256>>>(
            po, Wout + (size_t)l * INNERc * Dc, ph,
            Mr, Dc, INNERc, INNERc, Dc, Dc, bout + l * Dc, hin, 0);

        // --- feedforward block ---
        ln_kernel<<<Mr, 256>>>(ph, ln2w + l * Dc, ln2b + l * Dc, pn);
        gemm128_kernel<<<dim3(Fc / 128, Mr / 128), 256>>>(
            pn, W1 + (size_t)l * Dc * Fc, pff,
            Mr, Fc, Dc, Dc, Fc, Fc, b1 + l * Fc, nullptr, 1);
        float* cdst = (l == 5) ? out : ph;
        gemm128_kernel<<<dim3(Dc / 128, Mr / 128), 256>>>(
            pff, W2 + (size_t)l * Fc * Dc, cdst,
            Mr, Dc, Fc, Fc, Dc, Dc, b2 + l * Dc, ph, 0);
    }
}

// round 3
// speedup vs baseline: 2.0327x; 2.0327x over previous
#include <cuda_runtime.h>
#include <math.h>
#include <stdint.h>

// ---------------------------------------------------------------------------
// GraphTrajectoryEncoder: B=4, S=1024, D=512, DEPTH=6, H=8, HD=64, F=2048
// Round 3 (= Round 2 resubmit after infra failure):
// all matmuls on tensor cores via tf32 mma.sync (fp32 accumulate).
// ---------------------------------------------------------------------------

namespace {
constexpr int Bc = 4, Sc = 1024, Dc = 512, Hc = 8, HDc = 64, Fc = 2048;
constexpr int INNERc = 512;
constexpr int QKVC = 3 * INNERc;   // 1536
constexpr int Mr = Bc * Sc;        // 4096
}

// Scratch (allocation-free: module globals)
__device__ __align__(128) float g_n[Mr * Dc];
__device__ __align__(128) float g_qkv[Mr * QKVC];
__device__ __align__(128) float g_scores[(size_t)Bc * Hc * Sc * Sc];  // 128 MB
__device__ __align__(128) float g_o[Mr * INNERc];
__device__ __align__(128) float g_ff[Mr * Fc];
__device__ __align__(128) float g_h[Mr * Dc];
__device__ __align__(128) uint32_t g_pmask[(size_t)Bc * Sc * (Sc / 32)];  // 512 KB

// ---------------------------------------------------------------------------
// tf32 helpers
// ---------------------------------------------------------------------------
__device__ __forceinline__ uint32_t f2tf(float f) {
    uint32_t u;
    asm("cvt.rna.tf32.f32 %0, %1;" : "=r"(u) : "f"(f));
    return u;
}

__device__ __forceinline__ void mma_tf32(float c[4], uint32_t a0, uint32_t a1,
                                         uint32_t a2, uint32_t a3,
                                         uint32_t b0, uint32_t b1) {
    asm volatile(
        "mma.sync.aligned.m16n8k8.row.col.f32.tf32.tf32.f32 "
        "{%0,%1,%2,%3}, {%4,%5,%6,%7}, {%8,%9}, {%0,%1,%2,%3};\n"
        : "+f"(c[0]), "+f"(c[1]), "+f"(c[2]), "+f"(c[3])
        : "r"(a0), "r"(a1), "r"(a2), "r"(a3), "r"(b0), "r"(b1));
}

// ---------------------------------------------------------------------------
// Block-wide reduction for 256 threads
// ---------------------------------------------------------------------------
template <bool MAXOP>
__device__ __forceinline__ float block_reduce256(float v) {
    __shared__ float red[8];
    const int t = threadIdx.x;
#pragma unroll
    for (int o = 16; o > 0; o >>= 1) {
        float u = __shfl_down_sync(0xffffffffu, v, o);
        v = MAXOP ? fmaxf(v, u) : v + u;
    }
    if ((t & 31) == 0) red[t >> 5] = v;
    __syncthreads();
    if (t < 32) {
        v = (t < 8) ? red[t] : (MAXOP ? -INFINITY : 0.0f);
#pragma unroll
        for (int o = 4; o > 0; o >>= 1) {
            float u = __shfl_down_sync(0xffffffffu, v, o);
            v = MAXOP ? fmaxf(v, u) : v + u;
        }
        if (t == 0) red[0] = v;
    }
    __syncthreads();
    float r = red[0];
    __syncthreads();
    return r;
}

// ---------------------------------------------------------------------------
// LayerNorm over D=512, one block (256 threads) per row
// ---------------------------------------------------------------------------
__global__ void ln_kernel(const float* __restrict__ h, const float* __restrict__ w,
                          const float* __restrict__ b, float* __restrict__ out) {
    const int row = blockIdx.x;
    const int t = threadIdx.x;
    const float2 v = *reinterpret_cast<const float2*>(h + (size_t)row * Dc + t * 2);
    const float mean = block_reduce256<false>(v.x + v.y) * (1.0f / Dc);
    const float d0 = v.x - mean, d1 = v.y - mean;
    const float var = block_reduce256<false>(d0 * d0 + d1 * d1) * (1.0f / Dc);
    const float rstd = rsqrtf(var + 1e-5f);
    const float2 ww = *reinterpret_cast<const float2*>(w + t * 2);
    const float2 bb = *reinterpret_cast<const float2*>(b + t * 2);
    float2 o2 = make_float2(d0 * rstd * ww.x + bb.x, d1 * rstd * ww.y + bb.y);
    *reinterpret_cast<float2*>(out + (size_t)row * Dc + t * 2) = o2;
}

// ---------------------------------------------------------------------------
// Pack graph mask to bits (OR self-loop), once per launch.
// One thread per (b, r, c) element; ballot over 32 lanes -> 1 word.
// ---------------------------------------------------------------------------
__global__ void pack_mask_kernel(const int* __restrict__ gmask,
                                 uint32_t* __restrict__ pm) {
    const size_t idx = (size_t)blockIdx.x * 256 + threadIdx.x;  // over B*S*S
    const int c = (int)(idx & (Sc - 1));
    const int r = (int)((idx >> 10) & (Sc - 1));
    const bool keep = (gmask[idx] > 0) || (c == r);
    const uint32_t w = __ballot_sync(0xffffffffu, keep);
    if ((threadIdx.x & 31) == 0) pm[idx >> 5] = w;
}

// ---------------------------------------------------------------------------
// tf32 MMA GEMM: C[M,N] = A[M,K] @ B[K,N] (+bias)(gelu)(+res)
// 128x128 block tile, BK=16, 256 threads = 8 warps in 2(M)x4(N) grid.
// Warp tile 64x32 = 4(m) x 4(n) mma tiles of m16n8k8.
// ---------------------------------------------------------------------------
__global__ void __launch_bounds__(256, 2) gemm_tf32_kernel(
    const float* __restrict__ A, const float* __restrict__ B, float* __restrict__ C,
    int M, int N, int K, int lda, int ldb, int ldc,
    const float* __restrict__ bias, const float* __restrict__ res, int gelu) {
    __shared__ uint32_t As[16][132];  // k-major
    __shared__ uint32_t Bs[16][132];  // k-major
    const int tid = threadIdx.x;
    const int row0 = blockIdx.y * 128, col0 = blockIdx.x * 128;
    const int lane = tid & 31, wid = tid >> 5;
    const int g = lane >> 2, t = lane & 3;
    const int wm = (wid & 1) * 64, wn = (wid >> 1) * 32;

    const int ar = tid >> 1, akoff = (tid & 1) * 8;
    const float* Ap = A + (size_t)(row0 + ar) * lda + akoff;
    const int br0 = tid >> 5, bc = (tid & 31) * 4;
    const float* Bp = B + col0 + bc;

    float acc[4][4][4];
#pragma unroll
    for (int mi = 0; mi < 4; mi++)
#pragma unroll
        for (int ni = 0; ni < 4; ni++)
#pragma unroll
            for (int r = 0; r < 4; r++) acc[mi][ni][r] = 0.0f;

    for (int k0 = 0; k0 < K; k0 += 16) {
        const float4 va0 = *reinterpret_cast<const float4*>(Ap + k0);
        const float4 va1 = *reinterpret_cast<const float4*>(Ap + k0 + 4);
        const float4 vb0 = *reinterpret_cast<const float4*>(Bp + (size_t)(k0 + br0) * ldb);
        const float4 vb1 = *reinterpret_cast<const float4*>(Bp + (size_t)(k0 + br0 + 8) * ldb);
        __syncthreads();
        As[akoff + 0][ar] = f2tf(va0.x); As[akoff + 1][ar] = f2tf(va0.y);
        As[akoff + 2][ar] = f2tf(va0.z); As[akoff + 3][ar] = f2tf(va0.w);
        As[akoff + 4][ar] = f2tf(va1.x); As[akoff + 5][ar] = f2tf(va1.y);
        As[akoff + 6][ar] = f2tf(va1.z); As[akoff + 7][ar] = f2tf(va1.w);
        {
            uint4 u0 = make_uint4(f2tf(vb0.x), f2tf(vb0.y), f2tf(vb0.z), f2tf(vb0.w));
            uint4 u1 = make_uint4(f2tf(vb1.x), f2tf(vb1.y), f2tf(vb1.z), f2tf(vb1.w));
            *reinterpret_cast<uint4*>(&Bs[br0][bc]) = u0;
            *reinterpret_cast<uint4*>(&Bs[br0 + 8][bc]) = u1;
        }
        __syncthreads();
#pragma unroll
        for (int ks = 0; ks < 16; ks += 8) {
            uint32_t af[4][4], bf[4][2];
#pragma unroll
            for (int mi = 0; mi < 4; mi++) {
                const int m0 = wm + mi * 16 + g;
                af[mi][0] = As[ks + t][m0];
                af[mi][1] = As[ks + t][m0 + 8];
                af[mi][2] = As[ks + t + 4][m0];
                af[mi][3] = As[ks + t + 4][m0 + 8];
            }
#pragma unroll
            for (int ni = 0; ni < 4; ni++) {
                const int n0 = wn + ni * 8 + g;
                bf[ni][0] = Bs[ks + t][n0];
                bf[ni][1] = Bs[ks + t + 4][n0];
            }
#pragma unroll
            for (int mi = 0; mi < 4; mi++)
#pragma unroll
                for (int ni = 0; ni < 4; ni++)
                    mma_tf32(acc[mi][ni], af[mi][0], af[mi][1], af[mi][2], af[mi][3],
                             bf[ni][0], bf[ni][1]);
        }
    }

#pragma unroll
    for (int mi = 0; mi < 4; mi++) {
#pragma unroll
        for (int ni = 0; ni < 4; ni++) {
            const int cc = col0 + wn + ni * 8 + t * 2;
            float bx = 0.f, by = 0.f;
            if (bias) { bx = __ldg(&bias[cc]); by = __ldg(&bias[cc + 1]); }
#pragma unroll
            for (int half = 0; half < 2; half++) {
                const int r = row0 + wm + mi * 16 + g + half * 8;
                float v0 = acc[mi][ni][half * 2 + 0] + bx;
                float v1 = acc[mi][ni][half * 2 + 1] + by;
                if (gelu) {
                    v0 = 0.5f * v0 * (1.0f + erff(v0 * 0.7071067811865475f));
                    v1 = 0.5f * v1 * (1.0f + erff(v1 * 0.7071067811865475f));
                }
                if (res) {
                    const float2 rr = *reinterpret_cast<const float2*>(res + (size_t)r * ldc + cc);
                    v0 += rr.x; v1 += rr.y;
                }
                *reinterpret_cast<float2*>(C + (size_t)r * ldc + cc) = make_float2(v0, v1);
            }
        }
    }
}

// ---------------------------------------------------------------------------
// Scores via tf32 mma: S[i,j] = keep ? 0.125*(q_i.k_j) : -1e9
// A = Q rows, B = K rows. K-dim = HD = 64. grid (S/128, S/128, B*H)
// ---------------------------------------------------------------------------
__global__ void __launch_bounds__(256, 2) scores_tf32_kernel(
    const float* __restrict__ qkv, const uint32_t* __restrict__ pmask,
    float* __restrict__ scores) {
    __shared__ uint32_t As[16][132];
    __shared__ uint32_t Bs[16][132];
    const int tid = threadIdx.x;
    const int bh = blockIdx.z, b = bh >> 3, hh = bh & 7;
    const float* Q = qkv + (size_t)b * Sc * QKVC + hh * HDc;
    const float* Kp = Q + INNERc;
    const int row0 = blockIdx.y * 128, col0 = blockIdx.x * 128;
    const int lane = tid & 31, wid = tid >> 5;
    const int g = lane >> 2, t = lane & 3;
    const int wm = (wid & 1) * 64, wn = (wid >> 1) * 32;

    const int ar = tid >> 1, akoff = (tid & 1) * 8;
    const float* Ap = Q + (size_t)(row0 + ar) * QKVC + akoff;
    const float* Bp = Kp + (size_t)(col0 + ar) * QKVC + akoff;

    float acc[4][4][4];
#pragma unroll
    for (int mi = 0; mi < 4; mi++)
#pragma unroll
        for (int ni = 0; ni < 4; ni++)
#pragma unroll
            for (int r = 0; r < 4; r++) acc[mi][ni][r] = 0.0f;

    for (int k0 = 0; k0 < HDc; k0 += 16) {
        const float4 va0 = *reinterpret_cast<const float4*>(Ap + k0);
        const float4 va1 = *reinterpret_cast<const float4*>(Ap + k0 + 4);
        const float4 vb0 = *reinterpret_cast<const float4*>(Bp + k0);
        const float4 vb1 = *reinterpret_cast<const float4*>(Bp + k0 + 4);
        __syncthreads();
        As[akoff + 0][ar] = f2tf(va0.x); As[akoff + 1][ar] = f2tf(va0.y);
        As[akoff + 2][ar] = f2tf(va0.z); As[akoff + 3][ar] = f2tf(va0.w);
        As[akoff + 4][ar] = f2tf(va1.x); As[akoff + 5][ar] = f2tf(va1.y);
        As[akoff + 6][ar] = f2tf(va1.z); As[akoff + 7][ar] = f2tf(va1.w);
        Bs[akoff + 0][ar] = f2tf(vb0.x); Bs[akoff + 1][ar] = f2tf(vb0.y);
        Bs[akoff + 2][ar] = f2tf(vb0.z); Bs[akoff + 3][ar] = f2tf(vb0.w);
        Bs[akoff + 4][ar] = f2tf(vb1.x); Bs[akoff + 5][ar] = f2tf(vb1.y);
        Bs[akoff + 6][ar] = f2tf(vb1.z); Bs[akoff + 7][ar] = f2tf(vb1.w);
        __syncthreads();
#pragma unroll
        for (int ks = 0; ks < 16; ks += 8) {
            uint32_t af[4][4], bf[4][2];
#pragma unroll
            for (int mi = 0; mi < 4; mi++) {
                const int m0 = wm + mi * 16 + g;
                af[mi][0] = As[ks + t][m0];
                af[mi][1] = As[ks + t][m0 + 8];
                af[mi][2] = As[ks + t + 4][m0];
                af[mi][3] = As[ks + t + 4][m0 + 8];
            }
#pragma unroll
            for (int ni = 0; ni < 4; ni++) {
                const int n0 = wn + ni * 8 + g;
                bf[ni][0] = Bs[ks + t][n0];
                bf[ni][1] = Bs[ks + t + 4][n0];
            }
#pragma unroll
            for (int mi = 0; mi < 4; mi++)
#pragma unroll
                for (int ni = 0; ni < 4; ni++)
                    mma_tf32(acc[mi][ni], af[mi][0], af[mi][1], af[mi][2], af[mi][3],
                             bf[ni][0], bf[ni][1]);
        }
    }

    float* Sout = scores + (size_t)bh * Sc * Sc;
#pragma unroll
    for (int mi = 0; mi < 4; mi++) {
#pragma unroll
        for (int ni = 0; ni < 4; ni++) {
            const int cc = col0 + wn + ni * 8 + t * 2;
#pragma unroll
            for (int half = 0; half < 2; half++) {
                const int r = row0 + wm + mi * 16 + g + half * 8;
                const uint32_t mw = __ldg(&pmask[((size_t)b * Sc + r) * 32 + (cc >> 5)]);
                const float v0 = ((mw >> (cc & 31)) & 1u) ? acc[mi][ni][half * 2 + 0] * 0.125f : -1e9f;
                const float v1 = ((mw >> ((cc + 1) & 31)) & 1u) ? acc[mi][ni][half * 2 + 1] * 0.125f : -1e9f;
                *reinterpret_cast<float2*>(Sout + (size_t)r * Sc + cc) = make_float2(v0, v1);
            }
        }
    }
}

// ---------------------------------------------------------------------------
// Softmax in-place over rows of length S=1024. 1 block (256 thr) per row.
// ---------------------------------------------------------------------------
__global__ void softmax_kernel(float* __restrict__ scores) {
    float* p = scores + (size_t)blockIdx.x * Sc;
    const int t = threadIdx.x;
    float4 v = *reinterpret_cast<float4*>(p + t * 4);
    const float m = block_reduce256<true>(fmaxf(fmaxf(v.x, v.y), fmaxf(v.z, v.w)));
    const float e0 = __expf(v.x - m), e1 = __expf(v.y - m);
    const float e2 = __expf(v.z - m), e3 = __expf(v.w - m);
    const float s = block_reduce256<false>(e0 + e1 + e2 + e3);
    const float inv = 1.0f / s;
    *reinterpret_cast<float4*>(p + t * 4) = make_float4(e0 * inv, e1 * inv, e2 * inv, e3 * inv);
}

// ---------------------------------------------------------------------------
// PV via tf32 mma: o[b,s,h*64+d] = sum_j probs[bh,s,j] * v[b,j,h*64+d]
// 128x64 block tile, BK=16, K=S=1024. Warp grid 2(M)x4(N), warp tile 64x16.
// grid (1, S/128, B*H)
// ---------------------------------------------------------------------------
__global__ void __launch_bounds__(256, 2) pv_tf32_kernel(
    const float* __restrict__ scores, const float* __restrict__ qkv,
    float* __restrict__ o) {
    __shared__ uint32_t As[16][132];
    __shared__ uint32_t Bs[16][68];
    const int tid = threadIdx.x;
    const int bh = blockIdx.z, b = bh >> 3, hh = bh & 7;
    const float* P = scores + (size_t)bh * Sc * Sc;
    const float* V = qkv + (size_t)b * Sc * QKVC + 2 * INNERc + hh * HDc;
    float* Co = o + (size_t)b * Sc * INNERc + hh * HDc;
    const int row0 = blockIdx.y * 128;
    const int lane = tid & 31, wid = tid >> 5;
    const int g = lane >> 2, t = lane & 3;
    const int wm = (wid & 1) * 64, wn = (wid >> 1) * 16;

    const int ar = tid >> 1, akoff = (tid & 1) * 8;
    const float* Ap = P + (size_t)(row0 + ar) * Sc + akoff;
    const int br = tid >> 4, bcc = (tid & 15) * 4;
    const float* Bp = V + bcc;

    float acc[4][2][4];
#pragma unroll
    for (int mi = 0; mi < 4; mi++)
#pragma unroll
        for (int ni = 0; ni < 2; ni++)
#pragma unroll
            for (int r = 0; r < 4; r++) acc[mi][ni][r] = 0.0f;

    for (int k0 = 0; k0 < Sc; k0 += 16) {
        const float4 va0 = *reinterpret_cast<const float4*>(Ap + k0);
        const float4 va1 = *reinterpret_cast<const float4*>(Ap + k0 + 4);
        const float4 vb = *reinterpret_cast<const float4*>(Bp + (size_t)(k0 + br) * QKVC);
        __syncthreads();
        As[akoff + 0][ar] = f2tf(va0.x); As[akoff + 1][ar] = f2tf(va0.y);
        As[akoff + 2][ar] = f2tf(va0.z); As[akoff + 3][ar] = f2tf(va0.w);
        As[akoff + 4][ar] = f2tf(va1.x); As[akoff + 5][ar] = f2tf(va1.y);
        As[akoff + 6][ar] = f2tf(va1.z); As[akoff + 7][ar] = f2tf(va1.w);
        {
            uint4 u = make_uint4(f2tf(vb.x), f2tf(vb.y), f2tf(vb.z), f2tf(vb.w));
            *reinterpret_cast<uint4*>(&Bs[br][bcc]) = u;
        }
        __syncthreads();
#pragma unroll
        for (int ks = 0; ks < 16; ks += 8) {
            uint32_t af[4][4], bf[2][2];
#pragma unroll
            for (int mi = 0; mi < 4; mi++) {
                const int m0 = wm + mi * 16 + g;
                af[mi][0] = As[ks + t][m0];
                af[mi][1] = As[ks + t][m0 + 8];
                af[mi][2] = As[ks + t + 4][m0];
                af[mi][3] = As[ks + t + 4][m0 + 8];
            }
#pragma unroll
            for (int ni = 0; ni < 2; ni++) {
                const int n0 = wn + ni * 8 + g;
                bf[ni][0] = Bs[ks + t][n0];
                bf[ni][1] = Bs[ks + t + 4][n0];
            }
#pragma unroll
            for (int mi = 0; mi < 4; mi++)
#pragma unroll
                for (int ni = 0; ni < 2; ni++)
                    mma_tf32(acc[mi][ni], af[mi][0], af[mi][1], af[mi][2], af[mi][3],
                             bf[ni][0], bf[ni][1]);
        }
    }

#pragma unroll
    for (int mi = 0; mi < 4; mi++) {
#pragma unroll
        for (int ni = 0; ni < 2; ni++) {
            const int cc = wn + ni * 8 + t * 2;
#pragma unroll
            for (int half = 0; half < 2; half++) {
                const int r = row0 + wm + mi * 16 + g + half * 8;
                *reinterpret_cast<float2*>(Co + (size_t)r * INNERc + cc) =
                    make_float2(acc[mi][ni][half * 2 + 0], acc[mi][ni][half * 2 + 1]);
            }
        }
    }
}

// ---------------------------------------------------------------------------
// Host launcher
// ---------------------------------------------------------------------------
extern "C" void kernel_launch(void* const* d_in, const int* in_sizes, int n_in,
                              void* d_out, int out_size) {
    (void)in_sizes; (void)n_in; (void)out_size;
    const float* x     = (const float*)d_in[0];
    const int*   gmask = (const int*)d_in[1];
    const float* ln1w = (const float*)d_in[2];
    const float* ln1b = (const float*)d_in[3];
    const float* Wqkv = (const float*)d_in[4];
    const float* Wout = (const float*)d_in[5];
    const float* bout = (const float*)d_in[6];
    const float* ln2w = (const float*)d_in[7];
    const float* ln2b = (const float*)d_in[8];
    const float* W1   = (const float*)d_in[9];
    const float* b1   = (const float*)d_in[10];
    const float* W2   = (const float*)d_in[11];
    const float* b2   = (const float*)d_in[12];
    float* out = (float*)d_out;

    float *pn, *pqkv, *pscores, *po, *pff, *ph;
    uint32_t* ppm;
    cudaGetSymbolAddress((void**)&pn, g_n);
    cudaGetSymbolAddress((void**)&pqkv, g_qkv);
    cudaGetSymbolAddress((void**)&pscores, g_scores);
    cudaGetSymbolAddress((void**)&po, g_o);
    cudaGetSymbolAddress((void**)&pff, g_ff);
    cudaGetSymbolAddress((void**)&ph, g_h);
    cudaGetSymbolAddress((void**)&ppm, g_pmask);

    pack_mask_kernel<<<(Bc * Sc * Sc) / 256, 256>>>(gmask, ppm);

    for (int l = 0; l < 6; l++) {
        const float* hin = (l == 0) ? x : ph;

        // --- attention block ---
        ln_kernel<<<Mr, 256>>>(hin, ln1w + l * Dc, ln1b + l * Dc, pn);
        gemm_tf32_kernel<<<dim3(QKVC / 128, Mr / 128), 256>>>(
            pn, Wqkv + (size_t)l * Dc * QKVC, pqkv,
            Mr, QKVC, Dc, Dc, QKVC, QKVC, nullptr, nullptr, 0);
        scores_tf32_kernel<<<dim3(Sc / 128, Sc / 128, Bc * Hc), 256>>>(pqkv, ppm, pscores);
        softmax_kernel<<<Bc * Hc * Sc, 256>>>(pscores);
        pv_tf32_kernel<<<dim3(1, Sc / 128, Bc * Hc), 256>>>(pscores, pqkv, po);
        gemm_tf32_kernel<<<dim3(Dc / 128, Mr / 128), 256>>>(
            po, Wout + (size_t)l * INNERc * Dc, ph,
            Mr, Dc, INNERc, INNERc, Dc, Dc, bout + l * Dc, hin, 0);

        // --- feedforward block ---
        ln_kernel<<<Mr, 256>>>(ph, ln2w + l * Dc, ln2b + l * Dc, pn);
        gemm_tf32_kernel<<<dim3(Fc / 128, Mr / 128), 256>>>(
            pn, W1 + (size_t)l * Dc * Fc, pff,
            Mr, Fc, Dc, Dc, Fc, Fc, b1 + l * Fc, nullptr, 1);
        float* cdst = (l == 5) ? out : ph;
        gemm_tf32_kernel<<<dim3(Dc / 128, Mr / 128), 256>>>(
            pff, W2 + (size_t)l * Fc * Dc, cdst,
            Mr, Dc, Fc, Fc, Dc, Dc, b2 + l * Dc, ph, 0);
    }
}

// round 5
// speedup vs baseline: 2.8833x; 1.4185x over previous
#include <cuda_runtime.h>
#include <math.h>
#include <stdint.h>

// ---------------------------------------------------------------------------
// GraphTrajectoryEncoder: B=4, S=1024, D=512, DEPTH=6, H=8, HD=64, F=2048
// Round 5 (= Round 4 resubmit after infra failure):
// conflict-free smem + cp.async double-buffered tf32 mma pipelines.
// ---------------------------------------------------------------------------

namespace {
constexpr int Bc = 4, Sc = 1024, Dc = 512, Hc = 8, HDc = 64, Fc = 2048;
constexpr int INNERc = 512;
constexpr int QKVC = 3 * INNERc;   // 1536
constexpr int Mr = Bc * Sc;        // 4096
}

// Scratch (allocation-free: module globals)
__device__ __align__(128) float g_n[Mr * Dc];
__device__ __align__(128) float g_qkv[Mr * QKVC];
__device__ __align__(128) float g_scores[(size_t)Bc * Hc * Sc * Sc];  // 128 MB
__device__ __align__(128) float g_o[Mr * INNERc];
__device__ __align__(128) float g_ff[Mr * Fc];
__device__ __align__(128) float g_h[Mr * Dc];
__device__ __align__(128) uint32_t g_pmask[(size_t)Bc * Sc * (Sc / 32)];  // 512 KB

// ---------------------------------------------------------------------------
// helpers
// ---------------------------------------------------------------------------
__device__ __forceinline__ uint32_t f2tf(float f) {
    uint32_t u;
    asm("cvt.rna.tf32.f32 %0, %1;" : "=r"(u) : "f"(f));
    return u;
}

__device__ __forceinline__ void mma_tf32(float c[4], uint32_t a0, uint32_t a1,
                                         uint32_t a2, uint32_t a3,
                                         uint32_t b0, uint32_t b1) {
    asm volatile(
        "mma.sync.aligned.m16n8k8.row.col.f32.tf32.tf32.f32 "
        "{%0,%1,%2,%3}, {%4,%5,%6,%7}, {%8,%9}, {%0,%1,%2,%3};\n"
        : "+f"(c[0]), "+f"(c[1]), "+f"(c[2]), "+f"(c[3])
        : "r"(a0), "r"(a1), "r"(a2), "r"(a3), "r"(b0), "r"(b1));
}

__device__ __forceinline__ void cp16(void* smem, const void* gmem) {
    uint32_t s = (uint32_t)__cvta_generic_to_shared(smem);
    asm volatile("cp.async.cg.shared.global [%0], [%1], 16;" :: "r"(s), "l"(gmem));
}
#define CP_COMMIT() asm volatile("cp.async.commit_group;")
#define CP_WAIT1()  asm volatile("cp.async.wait_group 1;")

// ---------------------------------------------------------------------------
// Block-wide reduction for 256 threads
// ---------------------------------------------------------------------------
template <bool MAXOP>
__device__ __forceinline__ float block_reduce256(float v) {
    __shared__ float red[8];
    const int t = threadIdx.x;
#pragma unroll
    for (int o = 16; o > 0; o >>= 1) {
        float u = __shfl_down_sync(0xffffffffu, v, o);
        v = MAXOP ? fmaxf(v, u) : v + u;
    }
    if ((t & 31) == 0) red[t >> 5] = v;
    __syncthreads();
    if (t < 32) {
        v = (t < 8) ? red[t] : (MAXOP ? -INFINITY : 0.0f);
#pragma unroll
        for (int o = 4; o > 0; o >>= 1) {
            float u = __shfl_down_sync(0xffffffffu, v, o);
            v = MAXOP ? fmaxf(v, u) : v + u;
        }
        if (t == 0) red[0] = v;
    }
    __syncthreads();
    float r = red[0];
    __syncthreads();
    return r;
}

// ---------------------------------------------------------------------------
// LayerNorm over D=512, one block (256 threads) per row
// ---------------------------------------------------------------------------
__global__ void ln_kernel(const float* __restrict__ h, const float* __restrict__ w,
                          const float* __restrict__ b, float* __restrict__ out) {
    const int row = blockIdx.x;
    const int t = threadIdx.x;
    const float2 v = *reinterpret_cast<const float2*>(h + (size_t)row * Dc + t * 2);
    const float mean = block_reduce256<false>(v.x + v.y) * (1.0f / Dc);
    const float d0 = v.x - mean, d1 = v.y - mean;
    const float var = block_reduce256<false>(d0 * d0 + d1 * d1) * (1.0f / Dc);
    const float rstd = rsqrtf(var + 1e-5f);
    const float2 ww = *reinterpret_cast<const float2*>(w + t * 2);
    const float2 bb = *reinterpret_cast<const float2*>(b + t * 2);
    float2 o2 = make_float2(d0 * rstd * ww.x + bb.x, d1 * rstd * ww.y + bb.y);
    *reinterpret_cast<float2*>(out + (size_t)row * Dc + t * 2) = o2;
}

// ---------------------------------------------------------------------------
// Pack graph mask to bits (OR self-loop), once per launch.
// ---------------------------------------------------------------------------
__global__ void pack_mask_kernel(const int* __restrict__ gmask,
                                 uint32_t* __restrict__ pm) {
    const size_t idx = (size_t)blockIdx.x * 256 + threadIdx.x;  // over B*S*S
    const int c = (int)(idx & (Sc - 1));
    const int r = (int)((idx >> 10) & (Sc - 1));
    const bool keep = (gmask[idx] > 0) || (c == r);
    const uint32_t w = __ballot_sync(0xffffffffu, keep);
    if ((threadIdx.x & 31) == 0) pm[idx >> 5] = w;
}

// ---------------------------------------------------------------------------
// tf32 MMA GEMM: C[M,N] = A[M,K] @ B[K,N] (+bias)(gelu)(+res)
// 128x128 block tile, BK=16, 2-stage cp.async. 8 warps 2(M)x4(N).
// As: [m][k] stride 20 (conflict-free: bank=(20g+t)%32 distinct).
// Bs: [k][n] stride 136 (bank=(8t+g)%32 distinct).
// ---------------------------------------------------------------------------
__global__ void __launch_bounds__(256, 2) gemm_tf32_kernel(
    const float* __restrict__ A, const float* __restrict__ B, float* __restrict__ C,
    int M, int N, int K, int lda, int ldb, int ldc,
    const float* __restrict__ bias, const float* __restrict__ res, int gelu) {
    __shared__ float As[2][128 * 20];
    __shared__ float Bs[2][16 * 136];
    const int tid = threadIdx.x;
    const int row0 = blockIdx.y * 128, col0 = blockIdx.x * 128;
    const int lane = tid & 31, wid = tid >> 5;
    const int g = lane >> 2, t = lane & 3;
    const int wm = (wid & 1) * 64, wn = (wid >> 1) * 32;
    const int ar = tid >> 1, akoff = (tid & 1) * 8;
    const int br0 = tid >> 5, bc = (tid & 31) * 4;
    const float* Asrc = A + (size_t)(row0 + ar) * lda + akoff;
    const float* Bsrc = B + (size_t)br0 * ldb + col0 + bc;

    float acc[4][4][4] = {};
    const int ntiles = K >> 4;

    {   // prologue: tile 0 -> stage 0
        float* da = &As[0][ar * 20 + akoff];
        cp16(da, Asrc); cp16(da + 4, Asrc + 4);
        cp16(&Bs[0][br0 * 136 + bc], Bsrc);
        cp16(&Bs[0][(br0 + 8) * 136 + bc], Bsrc + (size_t)8 * ldb);
        CP_COMMIT();
    }
    for (int it = 0; it < ntiles; it++) {
        if (it + 1 < ntiles) {
            const int k0 = (it + 1) << 4;
            const int s = (it + 1) & 1;
            float* da = &As[s][ar * 20 + akoff];
            cp16(da, Asrc + k0); cp16(da + 4, Asrc + k0 + 4);
            cp16(&Bs[s][br0 * 136 + bc], Bsrc + (size_t)k0 * ldb);
            cp16(&Bs[s][(br0 + 8) * 136 + bc], Bsrc + (size_t)(k0 + 8) * ldb);
        }
        CP_COMMIT();
        CP_WAIT1();
        __syncthreads();
        const float* Sa = As[it & 1];
        const float* Sb = Bs[it & 1];
#pragma unroll
        for (int ks = 0; ks < 16; ks += 8) {
            uint32_t af[4][4], bf[4][2];
#pragma unroll
            for (int mi = 0; mi < 4; mi++) {
                const float* ap = Sa + (wm + mi * 16 + g) * 20 + ks;
                af[mi][0] = f2tf(ap[t]);
                af[mi][1] = f2tf(ap[160 + t]);       // +8 rows * 20
                af[mi][2] = f2tf(ap[t + 4]);
                af[mi][3] = f2tf(ap[160 + t + 4]);
            }
#pragma unroll
            for (int ni = 0; ni < 4; ni++) {
                const float* bp = Sb + (ks + t) * 136 + wn + ni * 8 + g;
                bf[ni][0] = f2tf(bp[0]);
                bf[ni][1] = f2tf(bp[4 * 136]);
            }
#pragma unroll
            for (int mi = 0; mi < 4; mi++)
#pragma unroll
                for (int ni = 0; ni < 4; ni++)
                    mma_tf32(acc[mi][ni], af[mi][0], af[mi][1], af[mi][2], af[mi][3],
                             bf[ni][0], bf[ni][1]);
        }
        __syncthreads();
    }

#pragma unroll
    for (int mi = 0; mi < 4; mi++) {
#pragma unroll
        for (int ni = 0; ni < 4; ni++) {
            const int cc = col0 + wn + ni * 8 + t * 2;
            float bx = 0.f, by = 0.f;
            if (bias) { bx = __ldg(&bias[cc]); by = __ldg(&bias[cc + 1]); }
#pragma unroll
            for (int half = 0; half < 2; half++) {
                const int r = row0 + wm + mi * 16 + g + half * 8;
                float v0 = acc[mi][ni][half * 2 + 0] + bx;
                float v1 = acc[mi][ni][half * 2 + 1] + by;
                if (gelu) {
                    v0 = 0.5f * v0 * (1.0f + erff(v0 * 0.7071067811865475f));
                    v1 = 0.5f * v1 * (1.0f + erff(v1 * 0.7071067811865475f));
                }
                if (res) {
                    const float2 rr = *reinterpret_cast<const float2*>(res + (size_t)r * ldc + cc);
                    v0 += rr.x; v1 += rr.y;
                }
                *reinterpret_cast<float2*>(C + (size_t)r * ldc + cc) = make_float2(v0, v1);
            }
        }
    }
}

// ---------------------------------------------------------------------------
// Scores: S[i,j] = keep ? 0.125*(q_i.k_j) : -1e9.
// Both Q and K tiles stored [row][k] stride 20 (conflict-free), cp.async 2-stage.
// grid (S/128, S/128, B*H)
// ---------------------------------------------------------------------------
__global__ void __launch_bounds__(256, 2) scores_tf32_kernel(
    const float* __restrict__ qkv, const uint32_t* __restrict__ pmask,
    float* __restrict__ scores) {
    __shared__ float As[2][128 * 20];
    __shared__ float Ks[2][128 * 20];
    const int tid = threadIdx.x;
    const int bh = blockIdx.z, b = bh >> 3, hh = bh & 7;
    const float* Q = qkv + (size_t)b * Sc * QKVC + hh * HDc;
    const float* Kp = Q + INNERc;
    const int row0 = blockIdx.y * 128, col0 = blockIdx.x * 128;
    const int lane = tid & 31, wid = tid >> 5;
    const int g = lane >> 2, t = lane & 3;
    const int wm = (wid & 1) * 64, wn = (wid >> 1) * 32;
    const int ar = tid >> 1, akoff = (tid & 1) * 8;
    const float* Asrc = Q + (size_t)(row0 + ar) * QKVC + akoff;
    const float* Bsrc = Kp + (size_t)(col0 + ar) * QKVC + akoff;

    float acc[4][4][4] = {};
    const int ntiles = HDc >> 4;  // 4

    {
        float* da = &As[0][ar * 20 + akoff];
        float* dk = &Ks[0][ar * 20 + akoff];
        cp16(da, Asrc); cp16(da + 4, Asrc + 4);
        cp16(dk, Bsrc); cp16(dk + 4, Bsrc + 4);
        CP_COMMIT();
    }
    for (int it = 0; it < ntiles; it++) {
        if (it + 1 < ntiles) {
            const int k0 = (it + 1) << 4;
            const int s = (it + 1) & 1;
            float* da = &As[s][ar * 20 + akoff];
            float* dk = &Ks[s][ar * 20 + akoff];
            cp16(da, Asrc + k0); cp16(da + 4, Asrc + k0 + 4);
            cp16(dk, Bsrc + k0); cp16(dk + 4, Bsrc + k0 + 4);
        }
        CP_COMMIT();
        CP_WAIT1();
        __syncthreads();
        const float* Sa = As[it & 1];
        const float* Sk = Ks[it & 1];
#pragma unroll
        for (int ks = 0; ks < 16; ks += 8) {
            uint32_t af[4][4], bf[4][2];
#pragma unroll
            for (int mi = 0; mi < 4; mi++) {
                const float* ap = Sa + (wm + mi * 16 + g) * 20 + ks;
                af[mi][0] = f2tf(ap[t]);
                af[mi][1] = f2tf(ap[160 + t]);
                af[mi][2] = f2tf(ap[t + 4]);
                af[mi][3] = f2tf(ap[160 + t + 4]);
            }
#pragma unroll
            for (int ni = 0; ni < 4; ni++) {
                const float* bp = Sk + (wn + ni * 8 + g) * 20 + ks;
                bf[ni][0] = f2tf(bp[t]);
                bf[ni][1] = f2tf(bp[t + 4]);
            }
#pragma unroll
            for (int mi = 0; mi < 4; mi++)
#pragma unroll
                for (int ni = 0; ni < 4; ni++)
                    mma_tf32(acc[mi][ni], af[mi][0], af[mi][1], af[mi][2], af[mi][3],
                             bf[ni][0], bf[ni][1]);
        }
        __syncthreads();
    }

    float* Sout = scores + (size_t)bh * Sc * Sc;
#pragma unroll
    for (int mi = 0; mi < 4; mi++) {
#pragma unroll
        for (int ni = 0; ni < 4; ni++) {
            const int cc = col0 + wn + ni * 8 + t * 2;
#pragma unroll
            for (int half = 0; half < 2; half++) {
                const int r = row0 + wm + mi * 16 + g + half * 8;
                const uint32_t mw = __ldg(&pmask[((size_t)b * Sc + r) * 32 + (cc >> 5)]);
                const float v0 = ((mw >> (cc & 31)) & 1u) ? acc[mi][ni][half * 2 + 0] * 0.125f : -1e9f;
                const float v1 = ((mw >> ((cc + 1) & 31)) & 1u) ? acc[mi][ni][half * 2 + 1] * 0.125f : -1e9f;
                *reinterpret_cast<float2*>(Sout + (size_t)r * Sc + cc) = make_float2(v0, v1);
            }
        }
    }
}

// ---------------------------------------------------------------------------
// Softmax in-place over rows of length S=1024. 1 block (256 thr) per row.
// ---------------------------------------------------------------------------
__global__ void softmax_kernel(float* __restrict__ scores) {
    float* p = scores + (size_t)blockIdx.x * Sc;
    const int t = threadIdx.x;
    float4 v = *reinterpret_cast<float4*>(p + t * 4);
    const float m = block_reduce256<true>(fmaxf(fmaxf(v.x, v.y), fmaxf(v.z, v.w)));
    const float e0 = __expf(v.x - m), e1 = __expf(v.y - m);
    const float e2 = __expf(v.z - m), e3 = __expf(v.w - m);
    const float s = block_reduce256<false>(e0 + e1 + e2 + e3);
    const float inv = 1.0f / s;
    *reinterpret_cast<float4*>(p + t * 4) = make_float4(e0 * inv, e1 * inv, e2 * inv, e3 * inv);
}

// ---------------------------------------------------------------------------
// PV: o = probs @ V. A = P tile [m][k] stride 20; B = V tile [k][n] stride 72.
// 128x64 block tile, BK=16, K=S=1024, 2-stage cp.async.
// grid (1, S/128, B*H). Warp grid 2(M)x4(N), warp tile 64x16.
// ---------------------------------------------------------------------------
__global__ void __launch_bounds__(256, 2) pv_tf32_kernel(
    const float* __restrict__ scores, const float* __restrict__ qkv,
    float* __restrict__ o) {
    __shared__ float As[2][128 * 20];
    __shared__ float Vs[2][16 * 72];
    const int tid = threadIdx.x;
    const int bh = blockIdx.z, b = bh >> 3, hh = bh & 7;
    const float* P = scores + (size_t)bh * Sc * Sc;
    const float* V = qkv + (size_t)b * Sc * QKVC + 2 * INNERc + hh * HDc;
    float* Co = o + (size_t)b * Sc * INNERc + hh * HDc;
    const int row0 = blockIdx.y * 128;
    const int lane = tid & 31, wid = tid >> 5;
    const int g = lane >> 2, t = lane & 3;
    const int wm = (wid & 1) * 64, wn = (wid >> 1) * 16;
    const int ar = tid >> 1, akoff = (tid & 1) * 8;
    const int vk = tid >> 4, vn = (tid & 15) * 4;
    const float* Asrc = P + (size_t)(row0 + ar) * Sc + akoff;
    const float* Vsrc = V + (size_t)vk * QKVC + vn;

    float acc[4][2][4] = {};
    const int ntiles = Sc >> 4;  // 64

    {
        float* da = &As[0][ar * 20 + akoff];
        cp16(da, Asrc); cp16(da + 4, Asrc + 4);
        cp16(&Vs[0][vk * 72 + vn], Vsrc);
        CP_COMMIT();
    }
    for (int it = 0; it < ntiles; it++) {
        if (it + 1 < ntiles) {
            const int k0 = (it + 1) << 4;
            const int s = (it + 1) & 1;
            float* da = &As[s][ar * 20 + akoff];
            cp16(da, Asrc + k0); cp16(da + 4, Asrc + k0 + 4);
            cp16(&Vs[s][vk * 72 + vn], Vsrc + (size_t)k0 * QKVC);
        }
        CP_COMMIT();
        CP_WAIT1();
        __syncthreads();
        const float* Sa = As[it & 1];
        const float* Sv = Vs[it & 1];
#pragma unroll
        for (int ks = 0; ks < 16; ks += 8) {
            uint32_t af[4][4], bf[2][2];
#pragma unroll
            for (int mi = 0; mi < 4; mi++) {
                const float* ap = Sa + (wm + mi * 16 + g) * 20 + ks;
                af[mi][0] = f2tf(ap[t]);
                af[mi][1] = f2tf(ap[160 + t]);
                af[mi][2] = f2tf(ap[t + 4]);
                af[mi][3] = f2tf(ap[160 + t + 4]);
            }
#pragma unroll
            for (int ni = 0; ni < 2; ni++) {
                const float* bp = Sv + (ks + t) * 72 + wn + ni * 8 + g;
                bf[ni][0] = f2tf(bp[0]);
                bf[ni][1] = f2tf(bp[4 * 72]);
            }
#pragma unroll
            for (int mi = 0; mi < 4; mi++)
#pragma unroll
                for (int ni = 0; ni < 2; ni++)
                    mma_tf32(acc[mi][ni], af[mi][0], af[mi][1], af[mi][2], af[mi][3],
                             bf[ni][0], bf[ni][1]);
        }
        __syncthreads();
    }

#pragma unroll
    for (int mi = 0; mi < 4; mi++) {
#pragma unroll
        for (int ni = 0; ni < 2; ni++) {
            const int cc = wn + ni * 8 + t * 2;
#pragma unroll
            for (int half = 0; half < 2; half++) {
                const int r = row0 + wm + mi * 16 + g + half * 8;
                *reinterpret_cast<float2*>(Co + (size_t)r * INNERc + cc) =
                    make_float2(acc[mi][ni][half * 2 + 0], acc[mi][ni][half * 2 + 1]);
            }
        }
    }
}

// ---------------------------------------------------------------------------
// Host launcher
// ---------------------------------------------------------------------------
extern "C" void kernel_launch(void* const* d_in, const int* in_sizes, int n_in,
                              void* d_out, int out_size) {
    (void)in_sizes; (void)n_in; (void)out_size;
    const float* x     = (const float*)d_in[0];
    const int*   gmask = (const int*)d_in[1];
    const float* ln1w = (const float*)d_in[2];
    const float* ln1b = (const float*)d_in[3];
    const float* Wqkv = (const float*)d_in[4];
    const float* Wout = (const float*)d_in[5];
    const float* bout = (const float*)d_in[6];
    const float* ln2w = (const float*)d_in[7];
    const float* ln2b = (const float*)d_in[8];
    const float* W1   = (const float*)d_in[9];
    const float* b1   = (const float*)d_in[10];
    const float* W2   = (const float*)d_in[11];
    const float* b2   = (const float*)d_in[12];
    float* out = (float*)d_out;

    float *pn, *pqkv, *pscores, *po, *pff, *ph;
    uint32_t* ppm;
    cudaGetSymbolAddress((void**)&pn, g_n);
    cudaGetSymbolAddress((void**)&pqkv, g_qkv);
    cudaGetSymbolAddress((void**)&pscores, g_scores);
    cudaGetSymbolAddress((void**)&po, g_o);
    cudaGetSymbolAddress((void**)&pff, g_ff);
    cudaGetSymbolAddress((void**)&ph, g_h);
    cudaGetSymbolAddress((void**)&ppm, g_pmask);

    pack_mask_kernel<<<(Bc * Sc * Sc) / 256, 256>>>(gmask, ppm);

    for (int l = 0; l < 6; l++) {
        const float* hin = (l == 0) ? x : ph;

        // --- attention block ---
        ln_kernel<<<Mr, 256>>>(hin, ln1w + l * Dc, ln1b + l * Dc, pn);
        gemm_tf32_kernel<<<dim3(QKVC / 128, Mr / 128), 256>>>(
            pn, Wqkv + (size_t)l * Dc * QKVC, pqkv,
            Mr, QKVC, Dc, Dc, QKVC, QKVC, nullptr, nullptr, 0);
        scores_tf32_kernel<<<dim3(Sc / 128, Sc / 128, Bc * Hc), 256>>>(pqkv, ppm, pscores);
        softmax_kernel<<<Bc * Hc * Sc, 256>>>(pscores);
        pv_tf32_kernel<<<dim3(1, Sc / 128, Bc * Hc), 256>>>(pscores, pqkv, po);
        gemm_tf32_kernel<<<dim3(Dc / 128, Mr / 128), 256>>>(
            po, Wout + (size_t)l * INNERc * Dc, ph,
            Mr, Dc, INNERc, INNERc, Dc, Dc, bout + l * Dc, hin, 0);

        // --- feedforward block ---
        ln_kernel<<<Mr, 256>>>(ph, ln2w + l * Dc, ln2b + l * Dc, pn);
        gemm_tf32_kernel<<<dim3(Fc / 128, Mr / 128), 256>>>(
            pn, W1 + (size_t)l * Dc * Fc, pff,
            Mr, Fc, Dc, Dc, Fc, Fc, b1 + l * Fc, nullptr, 1);
        float* cdst = (l == 5) ? out : ph;
        gemm_tf32_kernel<<<dim3(Dc / 128, Mr / 128), 256>>>(
            pff, W2 + (size_t)l * Fc * Dc, cdst,
            Mr, Dc, Fc, Fc, Dc, Dc, b2 + l * Dc, ph, 0);
    }
}

// round 7
// speedup vs baseline: 3.1361x; 1.0877x over previous
#include <cuda_runtime.h>
#include <math.h>
#include <stdint.h>

// ---------------------------------------------------------------------------
// GraphTrajectoryEncoder: B=4, S=1024, D=512, DEPTH=6, H=8, HD=64, F=2048
// Round 7 (= Round 6 resubmit after infra failure):
// flash-style fused masked attention (scores+softmax+PV in one kernel,
// no 128MB scores buffer) + R5's cp.async tf32 GEMMs.
// ---------------------------------------------------------------------------

namespace {
constexpr int Bc = 4, Sc = 1024, Dc = 512, Hc = 8, HDc = 64, Fc = 2048;
constexpr int INNERc = 512;
constexpr int QKVC = 3 * INNERc;   // 1536
constexpr int Mr = Bc * Sc;        // 4096
constexpr int FLASH_SMEM_FLOATS = 49664;   // Qs 8192 | Ks 2x8192 | Vs 8192 | Ps 16384 | red 512
constexpr int FLASH_SMEM_BYTES = FLASH_SMEM_FLOATS * 4;  // 198656
}

// Scratch (allocation-free: module globals)
__device__ __align__(128) float g_n[Mr * Dc];
__device__ __align__(128) float g_qkv[Mr * QKVC];
__device__ __align__(128) float g_o[Mr * INNERc];
__device__ __align__(128) float g_ff[Mr * Fc];
__device__ __align__(128) float g_h[Mr * Dc];
__device__ __align__(128) uint32_t g_pmask[(size_t)Bc * Sc * (Sc / 32)];  // 512 KB

// ---------------------------------------------------------------------------
// helpers
// ---------------------------------------------------------------------------
__device__ __forceinline__ uint32_t f2tf(float f) {
    uint32_t u;
    asm("cvt.rna.tf32.f32 %0, %1;" : "=r"(u) : "f"(f));
    return u;
}

__device__ __forceinline__ void mma_tf32(float c[4], uint32_t a0, uint32_t a1,
                                         uint32_t a2, uint32_t a3,
                                         uint32_t b0, uint32_t b1) {
    asm volatile(
        "mma.sync.aligned.m16n8k8.row.col.f32.tf32.tf32.f32 "
        "{%0,%1,%2,%3}, {%4,%5,%6,%7}, {%8,%9}, {%0,%1,%2,%3};\n"
        : "+f"(c[0]), "+f"(c[1]), "+f"(c[2]), "+f"(c[3])
        : "r"(a0), "r"(a1), "r"(a2), "r"(a3), "r"(b0), "r"(b1));
}

__device__ __forceinline__ void cp16(void* smem, const void* gmem) {
    uint32_t s = (uint32_t)__cvta_generic_to_shared(smem);
    asm volatile("cp.async.cg.shared.global [%0], [%1], 16;" :: "r"(s), "l"(gmem));
}
#define CP_COMMIT() asm volatile("cp.async.commit_group;")
#define CP_WAIT1()  asm volatile("cp.async.wait_group 1;")
#define CP_WAIT0()  asm volatile("cp.async.wait_group 0;")

// ---------------------------------------------------------------------------
// Block-wide reduction for 256 threads
// ---------------------------------------------------------------------------
template <bool MAXOP>
__device__ __forceinline__ float block_reduce256(float v) {
    __shared__ float red[8];
    const int t = threadIdx.x;
#pragma unroll
    for (int o = 16; o > 0; o >>= 1) {
        float u = __shfl_down_sync(0xffffffffu, v, o);
        v = MAXOP ? fmaxf(v, u) : v + u;
    }
    if ((t & 31) == 0) red[t >> 5] = v;
    __syncthreads();
    if (t < 32) {
        v = (t < 8) ? red[t] : (MAXOP ? -INFINITY : 0.0f);
#pragma unroll
        for (int o = 4; o > 0; o >>= 1) {
            float u = __shfl_down_sync(0xffffffffu, v, o);
            v = MAXOP ? fmaxf(v, u) : v + u;
        }
        if (t == 0) red[0] = v;
    }
    __syncthreads();
    float r = red[0];
    __syncthreads();
    return r;
}

// ---------------------------------------------------------------------------
// LayerNorm over D=512, one block (256 threads) per row
// ---------------------------------------------------------------------------
__global__ void ln_kernel(const float* __restrict__ h, const float* __restrict__ w,
                          const float* __restrict__ b, float* __restrict__ out) {
    const int row = blockIdx.x;
    const int t = threadIdx.x;
    const float2 v = *reinterpret_cast<const float2*>(h + (size_t)row * Dc + t * 2);
    const float mean = block_reduce256<false>(v.x + v.y) * (1.0f / Dc);
    const float d0 = v.x - mean, d1 = v.y - mean;
    const float var = block_reduce256<false>(d0 * d0 + d1 * d1) * (1.0f / Dc);
    const float rstd = rsqrtf(var + 1e-5f);
    const float2 ww = *reinterpret_cast<const float2*>(w + t * 2);
    const float2 bb = *reinterpret_cast<const float2*>(b + t * 2);
    float2 o2 = make_float2(d0 * rstd * ww.x + bb.x, d1 * rstd * ww.y + bb.y);
    *reinterpret_cast<float2*>(out + (size_t)row * Dc + t * 2) = o2;
}

// ---------------------------------------------------------------------------
// Pack graph mask to bits (OR self-loop), once per launch.
// ---------------------------------------------------------------------------
__global__ void pack_mask_kernel(const int* __restrict__ gmask,
                                 uint32_t* __restrict__ pm) {
    const size_t idx = (size_t)blockIdx.x * 256 + threadIdx.x;  // over B*S*S
    const int c = (int)(idx & (Sc - 1));
    const int r = (int)((idx >> 10) & (Sc - 1));
    const bool keep = (gmask[idx] > 0) || (c == r);
    const uint32_t w = __ballot_sync(0xffffffffu, keep);
    if ((threadIdx.x & 31) == 0) pm[idx >> 5] = w;
}

// ---------------------------------------------------------------------------
// tf32 MMA GEMM (unchanged from R5): C = A@B (+bias)(gelu)(+res)
// ---------------------------------------------------------------------------
__global__ void __launch_bounds__(256, 2) gemm_tf32_kernel(
    const float* __restrict__ A, const float* __restrict__ B, float* __restrict__ C,
    int M, int N, int K, int lda, int ldb, int ldc,
    const float* __restrict__ bias, const float* __restrict__ res, int gelu) {
    __shared__ float As[2][128 * 20];
    __shared__ float Bs[2][16 * 136];
    const int tid = threadIdx.x;
    const int row0 = blockIdx.y * 128, col0 = blockIdx.x * 128;
    const int lane = tid & 31, wid = tid >> 5;
    const int g = lane >> 2, t = lane & 3;
    const int wm = (wid & 1) * 64, wn = (wid >> 1) * 32;
    const int ar = tid >> 1, akoff = (tid & 1) * 8;
    const int br0 = tid >> 5, bc = (tid & 31) * 4;
    const float* Asrc = A + (size_t)(row0 + ar) * lda + akoff;
    const float* Bsrc = B + (size_t)br0 * ldb + col0 + bc;

    float acc[4][4][4] = {};
    const int ntiles = K >> 4;

    {
        float* da = &As[0][ar * 20 + akoff];
        cp16(da, Asrc); cp16(da + 4, Asrc + 4);
        cp16(&Bs[0][br0 * 136 + bc], Bsrc);
        cp16(&Bs[0][(br0 + 8) * 136 + bc], Bsrc + (size_t)8 * ldb);
        CP_COMMIT();
    }
    for (int it = 0; it < ntiles; it++) {
        if (it + 1 < ntiles) {
            const int k0 = (it + 1) << 4;
            const int s = (it + 1) & 1;
            float* da = &As[s][ar * 20 + akoff];
            cp16(da, Asrc + k0); cp16(da + 4, Asrc + k0 + 4);
            cp16(&Bs[s][br0 * 136 + bc], Bsrc + (size_t)k0 * ldb);
            cp16(&Bs[s][(br0 + 8) * 136 + bc], Bsrc + (size_t)(k0 + 8) * ldb);
        }
        CP_COMMIT();
        CP_WAIT1();
        __syncthreads();
        const float* Sa = As[it & 1];
        const float* Sb = Bs[it & 1];
#pragma unroll
        for (int ks = 0; ks < 16; ks += 8) {
            uint32_t af[4][4], bf[4][2];
#pragma unroll
            for (int mi = 0; mi < 4; mi++) {
                const float* ap = Sa + (wm + mi * 16 + g) * 20 + ks;
                af[mi][0] = f2tf(ap[t]);
                af[mi][1] = f2tf(ap[160 + t]);
                af[mi][2] = f2tf(ap[t + 4]);
                af[mi][3] = f2tf(ap[160 + t + 4]);
            }
#pragma unroll
            for (int ni = 0; ni < 4; ni++) {
                const float* bp = Sb + (ks + t) * 136 + wn + ni * 8 + g;
                bf[ni][0] = f2tf(bp[0]);
                bf[ni][1] = f2tf(bp[4 * 136]);
            }
#pragma unroll
            for (int mi = 0; mi < 4; mi++)
#pragma unroll
                for (int ni = 0; ni < 4; ni++)
                    mma_tf32(acc[mi][ni], af[mi][0], af[mi][1], af[mi][2], af[mi][3],
                             bf[ni][0], bf[ni][1]);
        }
        __syncthreads();
    }

#pragma unroll
    for (int mi = 0; mi < 4; mi++) {
#pragma unroll
        for (int ni = 0; ni < 4; ni++) {
            const int cc = col0 + wn + ni * 8 + t * 2;
            float bx = 0.f, by = 0.f;
            if (bias) { bx = __ldg(&bias[cc]); by = __ldg(&bias[cc + 1]); }
#pragma unroll
            for (int half = 0; half < 2; half++) {
                const int r = row0 + wm + mi * 16 + g + half * 8;
                float v0 = acc[mi][ni][half * 2 + 0] + bx;
                float v1 = acc[mi][ni][half * 2 + 1] + by;
                if (gelu) {
                    v0 = 0.5f * v0 * (1.0f + erff(v0 * 0.7071067811865475f));
                    v1 = 0.5f * v1 * (1.0f + erff(v1 * 0.7071067811865475f));
                }
                if (res) {
                    const float2 rr = *reinterpret_cast<const float2*>(res + (size_t)r * ldc + cc);
                    v0 += rr.x; v1 += rr.y;
                }
                *reinterpret_cast<float2*>(C + (size_t)r * ldc + cc) = make_float2(v0, v1);
            }
        }
    }
}

// ---------------------------------------------------------------------------
// Flash attention: per (q-tile of 128, b, h), loop k-tiles of 128:
//   S = mask(Q K^T * 0.125), online softmax, O += P V.  Never touches DRAM
//   for scores. tf32 mma, fp32 state. 256 threads, warp grid 2(M)x4(N).
// Smem (floats): Qs[128*64] | Ks[2][128*64] | Vs[128*64] | Ps[128*128] | red[512]
// Swizzles (conflict-free fragment loads):
//   A-type (Qs/Ks/Ps, row-major [r][k]): idx = r*LD + (k ^ ((r&7)<<2))
//   B-type (Vs, k-major [k][n]):         idx = k*64 + (n ^ ((k&3)<<3))
// ---------------------------------------------------------------------------
__global__ void __launch_bounds__(256, 1) flash_attn_kernel(
    const float* __restrict__ qkv, const uint32_t* __restrict__ pmask,
    float* __restrict__ o) {
    extern __shared__ float sm[];
    float* Qs = sm;                 // [128][64]
    float* KsB = sm + 8192;         // 2 x [128][64]
    float* Vs = sm + 24576;         // [128][64] (k rows)
    float* Ps = sm + 32768;         // [128][128]
    float* red = sm + 49152;        // [4][128]

    const int tid = threadIdx.x;
    const int row0 = blockIdx.x * 128;
    const int bh = blockIdx.y, b = bh >> 3, hh = bh & 7;
    const int lane = tid & 31, wid = tid >> 5;
    const int g = lane >> 2, t = lane & 3;
    const int wm = (wid & 1) * 64;          // M offset (S and O share rows)
    const int wn = (wid >> 1) * 32;         // S-tile N offset
    const int wno = (wid >> 1) * 16;        // O-tile N offset
    const int nw = wid >> 1;                // N-warp index

    const float* Qg = qkv + (size_t)(b * Sc + row0) * QKVC + hh * HDc;
    const float* Kg = qkv + (size_t)b * Sc * QKVC + INNERc + hh * HDc;
    const float* Vg = qkv + (size_t)b * Sc * QKVC + 2 * INNERc + hh * HDc;

    const int lr = tid >> 1;                // loader row 0..127
    const int lcb = (tid & 1) * 32;         // loader col base
    const int swA = (lr & 7) << 2;
    const int swV = (lr & 3) << 3;

    // prologue: Q tile + K tile 0  (group 0)
    {
        const float* qsrc = Qg + (size_t)lr * QKVC + lcb;
        float* qdst = Qs + lr * 64;
        const float* ksrc = Kg + (size_t)lr * QKVC + lcb;
        float* kdst = KsB + lr * 64;
#pragma unroll
        for (int j = 0; j < 8; j++) {
            cp16(qdst + ((lcb + 4 * j) ^ swA), qsrc + 4 * j);
            cp16(kdst + ((lcb + 4 * j) ^ swA), ksrc + 4 * j);
        }
        CP_COMMIT();
    }

    float oacc[4][2][4] = {};
    float mrun[4][2], lrun[4][2];
#pragma unroll
    for (int mi = 0; mi < 4; mi++) {
        mrun[mi][0] = -INFINITY; mrun[mi][1] = -INFINITY;
        lrun[mi][0] = 0.0f; lrun[mi][1] = 0.0f;
    }

    for (int kt = 0; kt < 8; kt++) {
        // prefetch next K tile (double-buffered) + this V tile (single buffer)
        if (kt + 1 < 8) {
            const float* ksrc = Kg + (size_t)((kt + 1) * 128 + lr) * QKVC + lcb;
            float* kdst = KsB + ((kt + 1) & 1) * 8192 + lr * 64;
#pragma unroll
            for (int j = 0; j < 8; j++) cp16(kdst + ((lcb + 4 * j) ^ swA), ksrc + 4 * j);
        }
        {
            const float* vsrc = Vg + (size_t)(kt * 128 + lr) * QKVC + lcb;
            float* vdst = Vs + lr * 64;
#pragma unroll
            for (int j = 0; j < 8; j++) cp16(vdst + ((lcb + 4 * j) ^ swV), vsrc + 4 * j);
        }
        CP_COMMIT();
        CP_WAIT1();
        __syncthreads();   // K tile kt (and Q) resident

        // ---- S = Q K^T ----
        const float* Kc = KsB + (kt & 1) * 8192;
        float sacc[4][4][4] = {};
#pragma unroll
        for (int ks = 0; ks < 64; ks += 8) {
            uint32_t af[4][4], bf[4][2];
#pragma unroll
            for (int mi = 0; mi < 4; mi++) {
                const float* q0 = Qs + (wm + mi * 16 + g) * 64;
                const float* q1 = q0 + 8 * 64;
                const int c0 = (ks + t) ^ (g << 2), c1 = (ks + t + 4) ^ (g << 2);
                af[mi][0] = f2tf(q0[c0]); af[mi][1] = f2tf(q1[c0]);
                af[mi][2] = f2tf(q0[c1]); af[mi][3] = f2tf(q1[c1]);
            }
#pragma unroll
            for (int ni = 0; ni < 4; ni++) {
                const float* kp = Kc + (wn + ni * 8 + g) * 64;
                bf[ni][0] = f2tf(kp[(ks + t) ^ (g << 2)]);
                bf[ni][1] = f2tf(kp[(ks + t + 4) ^ (g << 2)]);
            }
#pragma unroll
            for (int mi = 0; mi < 4; mi++)
#pragma unroll
                for (int ni = 0; ni < 4; ni++)
                    mma_tf32(sacc[mi][ni], af[mi][0], af[mi][1], af[mi][2], af[mi][3],
                             bf[ni][0], bf[ni][1]);
        }

        // ---- mask + scale + row max ----
        uint32_t mword[4][2];
#pragma unroll
        for (int mi = 0; mi < 4; mi++)
#pragma unroll
            for (int hf = 0; hf < 2; hf++) {
                const int row = row0 + wm + mi * 16 + g + 8 * hf;
                mword[mi][hf] = __ldg(&pmask[((size_t)b * Sc + row) * 32 + kt * 4 + (wn >> 5)]);
            }
        float cf[4][2];
#pragma unroll
        for (int mi = 0; mi < 4; mi++)
#pragma unroll
            for (int hf = 0; hf < 2; hf++) {
                float rmax = -INFINITY;
#pragma unroll
                for (int ni = 0; ni < 4; ni++)
#pragma unroll
                    for (int jj = 0; jj < 2; jj++) {
                        float v = sacc[mi][ni][hf * 2 + jj];
                        const bool keep = (mword[mi][hf] >> (ni * 8 + 2 * t + jj)) & 1u;
                        v = keep ? v * 0.125f : -1e9f;
                        sacc[mi][ni][hf * 2 + jj] = v;
                        rmax = fmaxf(rmax, v);
                    }
                rmax = fmaxf(rmax, __shfl_xor_sync(0xffffffffu, rmax, 1));
                rmax = fmaxf(rmax, __shfl_xor_sync(0xffffffffu, rmax, 2));
                if (t == 0) red[nw * 128 + wm + mi * 16 + g + 8 * hf] = rmax;
            }
        __syncthreads();   // sync1: per-warp row maxes visible

        // ---- combine maxes, exponentiate, partial sums ----
        float rsum[4][2];
#pragma unroll
        for (int mi = 0; mi < 4; mi++)
#pragma unroll
            for (int hf = 0; hf < 2; hf++) {
                const int row = wm + mi * 16 + g + 8 * hf;
                const float mt = fmaxf(fmaxf(red[row], red[128 + row]),
                                       fmaxf(red[256 + row], red[384 + row]));
                const float mo = mrun[mi][hf];
                const float mn = fmaxf(mo, mt);
                cf[mi][hf] = __expf(mo - mn);
                mrun[mi][hf] = mn;
                float s = 0.0f;
#pragma unroll
                for (int ni = 0; ni < 4; ni++)
#pragma unroll
                    for (int jj = 0; jj < 2; jj++) {
                        const float p = __expf(sacc[mi][ni][hf * 2 + jj] - mn);
                        sacc[mi][ni][hf * 2 + jj] = p;
                        s += p;
                    }
                s += __shfl_xor_sync(0xffffffffu, s, 1);
                s += __shfl_xor_sync(0xffffffffu, s, 2);
                rsum[mi][hf] = s;
            }
        __syncthreads();   // sync2: max reads done, red reusable

        // ---- write sums, stage P to smem, rescale O and l ----
#pragma unroll
        for (int mi = 0; mi < 4; mi++)
#pragma unroll
            for (int hf = 0; hf < 2; hf++)
                if (t == 0) red[nw * 128 + wm + mi * 16 + g + 8 * hf] = rsum[mi][hf];
#pragma unroll
        for (int mi = 0; mi < 4; mi++)
#pragma unroll
            for (int ni = 0; ni < 4; ni++)
#pragma unroll
                for (int hf = 0; hf < 2; hf++) {
                    const int row = wm + mi * 16 + g + 8 * hf;
                    const int c = (wn + ni * 8 + 2 * t) ^ (g << 2);
                    *reinterpret_cast<float2*>(&Ps[row * 128 + c]) =
                        make_float2(sacc[mi][ni][hf * 2], sacc[mi][ni][hf * 2 + 1]);
                }
#pragma unroll
        for (int mi = 0; mi < 4; mi++) {
            lrun[mi][0] *= cf[mi][0];
            lrun[mi][1] *= cf[mi][1];
#pragma unroll
            for (int ni = 0; ni < 2; ni++)
#pragma unroll
                for (int j = 0; j < 4; j++)
                    oacc[mi][ni][j] *= cf[mi][j >> 1];
        }
        CP_WAIT0();
        __syncthreads();   // sync3: V tile, P tile, row sums all visible

#pragma unroll
        for (int mi = 0; mi < 4; mi++)
#pragma unroll
            for (int hf = 0; hf < 2; hf++) {
                const int row = wm + mi * 16 + g + 8 * hf;
                lrun[mi][hf] += red[row] + red[128 + row] + red[256 + row] + red[384 + row];
            }

        // ---- O += P V ----
#pragma unroll 4
        for (int ks = 0; ks < 128; ks += 8) {
            uint32_t af[4][4], bf[2][2];
#pragma unroll
            for (int mi = 0; mi < 4; mi++) {
                const float* p0 = Ps + (wm + mi * 16 + g) * 128;
                const float* p1 = p0 + 8 * 128;
                const int c0 = (ks + t) ^ (g << 2), c1 = (ks + t + 4) ^ (g << 2);
                af[mi][0] = f2tf(p0[c0]); af[mi][1] = f2tf(p1[c0]);
                af[mi][2] = f2tf(p0[c1]); af[mi][3] = f2tf(p1[c1]);
            }
#pragma unroll
            for (int ni = 0; ni < 2; ni++) {
                const int n = wno + ni * 8 + g;
                bf[ni][0] = f2tf(Vs[(ks + t) * 64 + (n ^ (t << 3))]);
                bf[ni][1] = f2tf(Vs[(ks + t + 4) * 64 + (n ^ (t << 3))]);
            }
#pragma unroll
            for (int mi = 0; mi < 4; mi++)
#pragma unroll
                for (int ni = 0; ni < 2; ni++)
                    mma_tf32(oacc[mi][ni], af[mi][0], af[mi][1], af[mi][2], af[mi][3],
                             bf[ni][0], bf[ni][1]);
        }
        __syncthreads();   // sync4: P/Vs reusable next iter
    }

    // ---- epilogue: O /= l, write out ----
#pragma unroll
    for (int mi = 0; mi < 4; mi++)
#pragma unroll
        for (int ni = 0; ni < 2; ni++)
#pragma unroll
            for (int hf = 0; hf < 2; hf++) {
                const int row = row0 + wm + mi * 16 + g + 8 * hf;
                const int c = hh * HDc + wno + ni * 8 + 2 * t;
                const float il = 1.0f / lrun[mi][hf];
                *reinterpret_cast<float2*>(&o[(size_t)(b * Sc + row) * INNERc + c]) =
                    make_float2(oacc[mi][ni][hf * 2] * il, oacc[mi][ni][hf * 2 + 1] * il);
            }
}

// ---------------------------------------------------------------------------
// Host launcher
// ---------------------------------------------------------------------------
extern "C" void kernel_launch(void* const* d_in, const int* in_sizes, int n_in,
                              void* d_out, int out_size) {
    (void)in_sizes; (void)n_in; (void)out_size;
    const float* x     = (const float*)d_in[0];
    const int*   gmask = (const int*)d_in[1];
    const float* ln1w = (const float*)d_in[2];
    const float* ln1b = (const float*)d_in[3];
    const float* Wqkv = (const float*)d_in[4];
    const float* Wout = (const float*)d_in[5];
    const float* bout = (const float*)d_in[6];
    const float* ln2w = (const float*)d_in[7];
    const float* ln2b = (const float*)d_in[8];
    const float* W1   = (const float*)d_in[9];
    const float* b1   = (const float*)d_in[10];
    const float* W2   = (const float*)d_in[11];
    const float* b2   = (const float*)d_in[12];
    float* out = (float*)d_out;

    float *pn, *pqkv, *po, *pff, *ph;
    uint32_t* ppm;
    cudaGetSymbolAddress((void**)&pn, g_n);
    cudaGetSymbolAddress((void**)&pqkv, g_qkv);
    cudaGetSymbolAddress((void**)&po, g_o);
    cudaGetSymbolAddress((void**)&pff, g_ff);
    cudaGetSymbolAddress((void**)&ph, g_h);
    cudaGetSymbolAddress((void**)&ppm, g_pmask);

    cudaFuncSetAttribute(flash_attn_kernel,
                         cudaFuncAttributeMaxDynamicSharedMemorySize, FLASH_SMEM_BYTES);

    pack_mask_kernel<<<(Bc * Sc * Sc) / 256, 256>>>(gmask, ppm);

    for (int l = 0; l < 6; l++) {
        const float* hin = (l == 0) ? x : ph;

        // --- attention block ---
        ln_kernel<<<Mr, 256>>>(hin, ln1w + l * Dc, ln1b + l * Dc, pn);
        gemm_tf32_kernel<<<dim3(QKVC / 128, Mr / 128), 256>>>(
            pn, Wqkv + (size_t)l * Dc * QKVC, pqkv,
            Mr, QKVC, Dc, Dc, QKVC, QKVC, nullptr, nullptr, 0);
        flash_attn_kernel<<<dim3(Sc / 128, Bc * Hc), 256, FLASH_SMEM_BYTES>>>(
            pqkv, ppm, po);
        gemm_tf32_kernel<<<dim3(Dc / 128, Mr / 128), 256>>>(
            po, Wout + (size_t)l * INNERc * Dc, ph,
            Mr, Dc, INNERc, INNERc, Dc, Dc, bout + l * Dc, hin, 0);

        // --- feedforward block ---
        ln_kernel<<<Mr, 256>>>(ph, ln2w + l * Dc, ln2b + l * Dc, pn);
        gemm_tf32_kernel<<<dim3(Fc / 128, Mr / 128), 256>>>(
            pn, W1 + (size_t)l * Dc * Fc, pff,
            Mr, Fc, Dc, Dc, Fc, Fc, b1 + l * Fc, nullptr, 1);
        float* cdst = (l == 5) ? out : ph;
        gemm_tf32_kernel<<<dim3(Dc / 128, Mr / 128), 256>>>(
            pff, W2 + (size_t)l * Fc * Dc, cdst,
            Mr, Dc, Fc, Fc, Dc, Dc, b2 + l * Dc, ph, 0);
    }
}